// round 16
// baseline (speedup 1.0000x reference)
#include <cuda_runtime.h>

// rosa_emb_layer: B=8, T=2048, V=50257, C=768
// inputs: d_in[0] = idx (B,T) int32, d_in[1] = emb (V,C) float32
// output: (B,T,C) float32
//
// R16 = R15 fork-join with the fixup grid bug fixed (needed 64 CTAs to
// cover all 16384 rows; R15 launched 8, dropping 7/8 of matched rows --
// and since the output norm lives entirely in the ~42 matched rows,
// rel_err was ~0.94). Structure: zero_kernel (50MB store drain, ~9.9us)
// runs CONCURRENTLY with match_kernel (bloom-accelerated suffix match,
// writes per-row tok to __device__ scratch, ~6-7us); fixup joins and
// overwrites matched rows with emb data.
// (L<<11)|j integer max == argmax(L + j*1e-5) with larger-j tie-break.

#define TT 2048
#define BB 8
#define CC 768
#define WPB 8
#define NCHUNK (TT / 128)
#define SIGW 32

__device__ int g_tok[BB * TT];   // per-row predicted token, -1 = no match

__device__ __forceinline__ void stg_v8(float* p, const float* r) {
    asm volatile("st.global.v8.f32 [%0], {%1,%2,%3,%4,%5,%6,%7,%8};"
                 :: "l"(p), "f"(r[0]), "f"(r[1]), "f"(r[2]), "f"(r[3]),
                    "f"(r[4]), "f"(r[5]), "f"(r[6]), "f"(r[7]) : "memory");
}

__device__ __forceinline__ void stg_v8_zero(float* p) {
    asm volatile("st.global.v8.f32 [%0], {%1,%1,%1,%1,%1,%1,%1,%1};"
                 :: "l"(p), "f"(0.0f) : "memory");
}

__device__ __forceinline__ void ldg_v8(const float* p, float* r) {
    asm volatile("ld.global.nc.v8.f32 {%0,%1,%2,%3,%4,%5,%6,%7}, [%8];"
                 : "=f"(r[0]), "=f"(r[1]), "=f"(r[2]), "=f"(r[3]),
                   "=f"(r[4]), "=f"(r[5]), "=f"(r[6]), "=f"(r[7])
                 : "l"(p));
}

// ---- Node A: pure zero-fill of the 50MB output (store-drain bound). ----
__global__ __launch_bounds__(256)
void zero_kernel(float* __restrict__ out) {
    const size_t t = (size_t)blockIdx.x * 256 + threadIdx.x;
    float* p = out + t * 8;
    const size_t stride = (size_t)512 * 256 * 8;
    #pragma unroll
    for (int k = 0; k < 12; k++)
        stg_v8_zero(p + k * stride);
}

// ---- Node B: bloom-accelerated match, writes g_tok only (no output). ----
__global__ __launch_bounds__(256, 8)
void match_kernel(const int* __restrict__ idx) {
    __shared__ int      xs[TT];
    __shared__ unsigned sig[NCHUNK * SIGW];

    const int cta_per_b = TT / WPB;
    const int b      = blockIdx.x / cta_per_b;
    const int i_base = (blockIdx.x % cta_per_b) * WPB;
    const int tid  = threadIdx.x;
    const int w    = tid >> 5;
    const int lane = tid & 31;
    const int i    = i_base + w;

    const int4* g  = (const int4*)(idx + (size_t)b * TT);
    int4*       s4 = (int4*)xs;
    s4[tid]       = g[tid];
    s4[tid + 256] = g[tid + 256];
    ((uint2*)sig)[tid] = make_uint2(0u, 0u);
    __syncthreads();

    #pragma unroll
    for (int k = 0; k < TT / 256; k++) {
        const int p = tid + 256 * k;
        const unsigned hh = (unsigned)xs[p] & 1023u;
        atomicOr(&sig[(p >> 7) * SIGW + (hh >> 5)], 1u << (hh & 31));
    }
    __syncthreads();

    const int      xi = xs[i];
    const unsigned h  = (unsigned)xi & 1023u;
    int best = 0;                       // (L<<11)|j ; 0 == no match

    const int nc = i >> 7;
    bool hit = false;
    if (lane < nc)
        hit = (sig[lane * SIGW + (h >> 5)] >> (h & 31)) & 1u;
    unsigned cmask = __ballot_sync(0xffffffffu, hit);

    while (cmask) {                     // hit chunks: ~1 avg (true + FP)
        const int c = __ffs(cmask) - 1;
        cmask &= cmask - 1;
        const int j0 = (c << 7) + lane * 4;
        const int4 v = s4[j0 >> 2];
        #pragma unroll
        for (int q = 0; q < 4; q++) {
            const int e = (q == 0) ? v.x : (q == 1) ? v.y : (q == 2) ? v.z : v.w;
            if (e == xi) {
                const int j = j0 + q;
                int L = 1, t = 1;
                while (t <= j && xs[i - t] == xs[j - t]) { ++L; ++t; }
                const int p = (L << 11) | j;
                if (p > best) best = p;
            }
        }
    }
    {   // masked tail chunk [nc*128, i)
        const int j0 = (nc << 7) + lane * 4;
        if (j0 < i) {
            const int4 v = s4[j0 >> 2];
            const bool m0 = (v.x == xi);
            const bool m1 = (v.y == xi) & (j0 + 1 < i);
            const bool m2 = (v.z == xi) & (j0 + 2 < i);
            const bool m3 = (v.w == xi) & (j0 + 3 < i);
            if (m0 | m1 | m2 | m3) {
                #pragma unroll
                for (int q = 0; q < 4; q++) {
                    const bool m = (q == 0) ? m0 : (q == 1) ? m1 : (q == 2) ? m2 : m3;
                    if (m) {
                        const int j = j0 + q;
                        int L = 1, t = 1;
                        while (t <= j && xs[i - t] == xs[j - t]) { ++L; ++t; }
                        const int p = (L << 11) | j;
                        if (p > best) best = p;
                    }
                }
            }
        }
    }

    #pragma unroll
    for (int o = 16; o; o >>= 1)
        best = max(best, __shfl_xor_sync(0xffffffffu, best, o));

    if (lane == 0) {
        int tok = -1;
        if (best >= (1 << 11)) {
            int pidx = (best & 2047) + 1;
            if (pidx > TT - 1) pidx = TT - 1;
            tok = xs[pidx];
        }
        g_tok[b * TT + i] = tok;
    }
}

// ---- Node C (join): overwrite the rare matched rows with emb data. ----
// 64 CTAs x 8 warps = 512 warps; each warp scans 32 rows' toks via ballot.
__global__ __launch_bounds__(256)
void fixup_kernel(const float* __restrict__ emb, float* __restrict__ out) {
    const int wg   = blockIdx.x * 8 + (threadIdx.x >> 5);
    const int lane = threadIdx.x & 31;
    const int t    = g_tok[wg * 32 + lane];
    unsigned m = __ballot_sync(0xffffffffu, t >= 0);
    while (m) {
        const int c = __ffs(m) - 1;
        m &= m - 1;
        const int tok = __shfl_sync(0xffffffffu, t, c);
        const int row = wg * 32 + c;
        const float* e = emb + (size_t)tok * CC;
        float*       o = out + (size_t)row * CC;
        float rv[24];
        #pragma unroll
        for (int k = 0; k < 3; k++) ldg_v8(e + (lane + 32 * k) * 8, rv + 8 * k);
        #pragma unroll
        for (int k = 0; k < 3; k++) stg_v8(o + (lane + 32 * k) * 8, rv + 8 * k);
    }
}

extern "C" void kernel_launch(void* const* d_in, const int* in_sizes, int n_in,
                              void* d_out, int out_size) {
    const int*   idx = (const int*)d_in[0];
    const float* emb = (const float*)d_in[1];
    float*       out = (float*)d_out;

    // Fork-join: match on side stream concurrent with zero_kernel; both
    // complete before fixup. Streams/events are host objects (no device mem).
    cudaStream_t s2;
    cudaStreamCreateWithFlags(&s2, cudaStreamNonBlocking);
    cudaEvent_t e1, e2;
    cudaEventCreateWithFlags(&e1, cudaEventDisableTiming);
    cudaEventCreateWithFlags(&e2, cudaEventDisableTiming);

    cudaEventRecord(e1, 0);
    cudaStreamWaitEvent(s2, e1, 0);
    match_kernel<<<BB * (TT / WPB), 256, 0, s2>>>(idx);   // fork branch
    cudaEventRecord(e2, s2);

    zero_kernel<<<512, 256>>>(out);                       // main branch
    cudaStreamWaitEvent(0, e2, 0);                        // join
    fixup_kernel<<<BB * TT / (8 * 32), 256>>>(emb, out);  // 64 CTAs

    // (streams/events intentionally not destroyed during capture)
}

// round 17
// speedup vs baseline: 1.5775x; 1.5775x over previous
#include <cuda_runtime.h>

// rosa_emb_layer: B=8, T=2048, V=50257, C=768
// inputs: d_in[0] = idx (B,T) int32, d_in[1] = emb (V,C) float32
// output: (B,T,C) float32
//
// R17: ONE-WAVE fused kernel = the untested combination of three
// individually-validated pieces:
//  (1) 1024 CTAs x 256 thr -> ALL resident (0.86 wave): kills the wave
//      serialization that pinned every 2048-CTA variant at ~12.8.
//  (2) Phase-0 optimistic zero stores from every warp at cycle 0: the
//      9.9us 50MB store drain starts immediately, chip-wide (R6's version
//      failed only because wave-2 stores started ~7us late).
//  (3) Bloom chunk signatures -> ~2 scan trips per warp instead of 12
//      (fixes exactly what sank the R11 one-wave grid).
// 2 strided rows per warp (i, i+1024: equal work per warp). Matched rows
// (~42 total) overwritten at the end (same lanes, same addresses).
// (L<<11)|j integer max == argmax(L + j*1e-5) with larger-j tie-break.

#define TT 2048
#define BB 8
#define CC 768
#define NCHUNK (TT / 128)   // 16
#define SIGW 32             // 1024-bit bloom per chunk

__device__ __forceinline__ void stg_v8(float* p, const float* r) {
    asm volatile("st.global.v8.f32 [%0], {%1,%2,%3,%4,%5,%6,%7,%8};"
                 :: "l"(p), "f"(r[0]), "f"(r[1]), "f"(r[2]), "f"(r[3]),
                    "f"(r[4]), "f"(r[5]), "f"(r[6]), "f"(r[7]) : "memory");
}

__device__ __forceinline__ void stg_v8_zero(float* p) {
    asm volatile("st.global.v8.f32 [%0], {%1,%1,%1,%1,%1,%1,%1,%1};"
                 :: "l"(p), "f"(0.0f) : "memory");
}

__device__ __forceinline__ void ldg_v8(const float* p, float* r) {
    asm volatile("ld.global.nc.v8.f32 {%0,%1,%2,%3,%4,%5,%6,%7}, [%8];"
                 : "=f"(r[0]), "=f"(r[1]), "=f"(r[2]), "=f"(r[3]),
                   "=f"(r[4]), "=f"(r[5]), "=f"(r[6]), "=f"(r[7])
                 : "l"(p));
}

// Scan one full 128-token chunk c for token x against row i (rare path).
__device__ __forceinline__ void scan_chunk(const int4* s4, const int* xs,
                                           int c, int lane, int x, int i,
                                           int& best) {
    const int j0 = (c << 7) + lane * 4;
    const int4 v = s4[j0 >> 2];
    #pragma unroll
    for (int q = 0; q < 4; q++) {
        const int e = (q == 0) ? v.x : (q == 1) ? v.y : (q == 2) ? v.z : v.w;
        if (e == x) {
            const int j = j0 + q;
            int L = 1, t = 1;
            while (t <= j && xs[i - t] == xs[j - t]) { ++L; ++t; }
            const int p = (L << 11) | j;
            if (p > best) best = p;
        }
    }
}

// Masked tail chunk [c*128, i) for token x against row i.
__device__ __forceinline__ void scan_tail(const int4* s4, const int* xs,
                                          int c, int lane, int x, int i,
                                          int& best) {
    const int j0 = (c << 7) + lane * 4;
    if (j0 < i) {
        const int4 v = s4[j0 >> 2];
        #pragma unroll
        for (int q = 0; q < 4; q++) {
            const int e = (q == 0) ? v.x : (q == 1) ? v.y : (q == 2) ? v.z : v.w;
            if (e == x && (j0 + q < i)) {
                const int j = j0 + q;
                int L = 1, t = 1;
                while (t <= j && xs[i - t] == xs[j - t]) { ++L; ++t; }
                const int p = (L << 11) | j;
                if (p > best) best = p;
            }
        }
    }
}

__global__ __launch_bounds__(256, 7)
void rosa_fused_kernel(const int* __restrict__ idx,
                       const float* __restrict__ emb,
                       float* __restrict__ out) {
    __shared__ int      xs[TT];
    __shared__ unsigned sig[NCHUNK * SIGW];

    const int b    = blockIdx.x >> 7;            // 128 CTAs per batch
    const int rb   = (blockIdx.x & 127) * 8;
    const int tid  = threadIdx.x;
    const int w    = tid >> 5;
    const int lane = tid & 31;
    const int iA   = rb + w;                     // [0, 1024)
    const int iB   = iA + 1024;                  // [1024, 2048)

    // ---- Phase 0: fire both rows' zero stores at cycle 0 (no deps). ----
    float* oA = out + ((size_t)b * TT + iA) * CC;
    float* oB = oA + (size_t)1024 * CC;
    #pragma unroll
    for (int k = 0; k < 3; k++) {
        stg_v8_zero(oA + (lane + 32 * k) * 8);
        stg_v8_zero(oB + (lane + 32 * k) * 8);
    }

    // ---- Phase 1: fill token row (8 KB) + bloom signatures (2 KB). ----
    const int4* g  = (const int4*)(idx + (size_t)b * TT);
    int4*       s4 = (int4*)xs;
    s4[tid]       = g[tid];
    s4[tid + 256] = g[tid + 256];
    ((uint2*)sig)[tid] = make_uint2(0u, 0u);
    __syncthreads();
    #pragma unroll
    for (int k = 0; k < TT / 256; k++) {
        const int p = tid + 256 * k;
        const unsigned hh = (unsigned)xs[p] & 1023u;
        atomicOr(&sig[(p >> 7) * SIGW + (hh >> 5)], 1u << (hh & 31));
    }
    __syncthreads();

    const int xA = xs[iA], xB = xs[iB];
    const unsigned hA = (unsigned)xA & 1023u;
    const unsigned hB = (unsigned)xB & 1023u;
    int bestA = 0, bestB = 0;          // (L<<11)|j ; 0 == no match

    // ---- Phase 2: parallel bloom tests (lane c tests chunk c). ----
    const int ncA = iA >> 7;           // full chunks below iA (0..7)
    const int ncB = iB >> 7;           // full chunks below iB (8..15)
    bool hitA = (lane < ncA) && ((sig[lane * SIGW + (hA >> 5)] >> (hA & 31)) & 1u);
    bool hitB = (lane < ncB) && ((sig[lane * SIGW + (hB >> 5)] >> (hB & 31)) & 1u);
    unsigned mA = __ballot_sync(0xffffffffu, hitA);
    unsigned mB = __ballot_sync(0xffffffffu, hitB);

    while (mA) { const int c = __ffs(mA) - 1; mA &= mA - 1;
                 scan_chunk(s4, xs, c, lane, xA, iA, bestA); }
    while (mB) { const int c = __ffs(mB) - 1; mB &= mB - 1;
                 scan_chunk(s4, xs, c, lane, xB, iB, bestB); }
    scan_tail(s4, xs, ncA, lane, xA, iA, bestA);
    scan_tail(s4, xs, ncB, lane, xB, iB, bestB);

    // ---- Phase 3: reduce + rare matched-row overwrite. ----
    #pragma unroll
    for (int o = 16; o; o >>= 1) {
        bestA = max(bestA, __shfl_xor_sync(0xffffffffu, bestA, o));
        bestB = max(bestB, __shfl_xor_sync(0xffffffffu, bestB, o));
    }

    #pragma unroll
    for (int r = 0; r < 2; r++) {
        const int bst = r ? bestB : bestA;
        if (bst >= (1 << 11)) {        // rare: ~42 rows in the whole problem
            int pidx = (bst & 2047) + 1;
            if (pidx > TT - 1) pidx = TT - 1;
            const int tok = xs[pidx];
            const float* erow = emb + (size_t)tok * CC;
            float* orow = r ? oB : oA;
            float rv[24];
            #pragma unroll
            for (int k = 0; k < 3; k++)
                ldg_v8(erow + (lane + 32 * k) * 8, rv + 8 * k);
            #pragma unroll
            for (int k = 0; k < 3; k++)
                stg_v8(orow + (lane + 32 * k) * 8, rv + 8 * k);
        }
    }
}

extern "C" void kernel_launch(void* const* d_in, const int* in_sizes, int n_in,
                              void* d_out, int out_size) {
    const int*   idx = (const int*)d_in[0];
    const float* emb = (const float*)d_in[1];
    float*       out = (float*)d_out;

    rosa_fused_kernel<<<BB * 128, 256>>>(idx, emb, out);
}